// round 12
// baseline (speedup 1.0000x reference)
#include <cuda_runtime.h>
#include <stdint.h>

// LengthRegulator, fused single-launch.
//   out[n, t, :] = x[n, searchsorted(csum[n], t, 'right'), :] for t < total[n], else 0
//   mel_pos = [1..T] appended after the frames.
//
// Output layout (validated via out_size divisibility, N*C = 24576):
//   case A: [ out: N*T*C f32 ][ mel_pos: T f32 ]
//   case B: [ out: N*T*C f32 ][ mel_pos: T i64 ]
//
// R12 = R7 grid (SLICES=16, 1024 blocks, one resident wave -> best bench gap)
//     x R10 copy loop (front-loaded ids via LDS.128, select-then-store-
//       immediately, regs 26 -> best kernel dur 41.4us). R9 tried this pairing
//       but with a vals[8] staging array (regs 54) — removed here.
//       Per-thread range rounded to multiple of 8 so batches stay aligned
//       and fully unrolled; scalar tail only in the last partial batch.

#define L_LEN    256
#define THREADS  288           // 3 frame-groups x 96 channel chunks
#define SLICES   16
#define FMAX     272           // fpb <= 256 for T <= 4096

__global__ __launch_bounds__(THREADS)
void lr_onewave_kernel(const float* __restrict__ x,
                       const int* __restrict__ dur,
                       float* __restrict__ out,
                       float* __restrict__ mp,
                       int T, int mel_is_i64)
{
    const int n    = blockIdx.x;
    const int s    = blockIdx.y;
    const int tid  = threadIdx.x;
    const int wid  = tid >> 5;
    const int lane = tid & 31;

    const int fpb     = (T + SLICES - 1) / SLICES;     // frames per block
    const int t_begin = s * fpb;
    const int t_end   = (t_begin + fpb < T) ? (t_begin + fpb) : T;
    const int nf      = t_end - t_begin;
    if (nf <= 0) return;

    __shared__ int csum[L_LEN];
    __shared__ int wsum[8];
    __shared__ int fidx[FMAX];

    // ---- mel_pos: row-0 blocks write their slice ----
    if (n == 0) {
        for (int f = tid; f < nf; f += THREADS) {
            int t = t_begin + f;
            if (mel_is_i64) ((long long*)mp)[t] = (long long)(t + 1);
            else            mp[t] = (float)(t + 1);
        }
    }

    // ---- inclusive prefix sum of durations (shuffle scan, warps 0..7) ----
    int v = 0;
    if (tid < L_LEN) {
        v = dur[n * L_LEN + tid];
        #pragma unroll
        for (int off = 1; off < 32; off <<= 1) {
            int u = __shfl_up_sync(0xFFFFFFFFu, v, off);
            if (lane >= off) v += u;
        }
        if (lane == 31) wsum[wid] = v;
    }
    __syncthreads();
    if (wid == 0 && lane < 8) {
        int t = wsum[lane];
        #pragma unroll
        for (int off = 1; off < 8; off <<= 1) {
            int u = __shfl_up_sync(0xFFu, t, off);
            if (lane >= off) t += u;
        }
        wsum[lane] = t;
    }
    __syncthreads();
    if (tid < L_LEN) csum[tid] = v + (wid > 0 ? wsum[wid - 1] : 0);
    __syncthreads();

    const int total = csum[L_LEN - 1];

    // ---- binary search source row for each frame of this chunk ----
    for (int f = tid; f < nf; f += THREADS) {
        int t  = t_begin + f;
        int id = -1;
        if (t < total) {
            int lo = 0, hi = L_LEN;
            while (lo < hi) {
                int mid = (lo + hi) >> 1;
                if (csum[mid] > t) hi = mid; else lo = mid + 1;
            }
            id = (lo < L_LEN) ? lo : (L_LEN - 1);
        }
        fidx[f] = id;
    }
    __syncthreads();

    // ---- streaming copy: batches of 8 frames, R10 loop shape ----
    const int g = tid / 96;                // frame-group 0..2 (whole warps)
    const int c = tid - g * 96;            // channel chunk 0..95

    // round per-group range to multiple of 8 so f0 is int4-aligned in fidx
    const int fpg = ((nf + 23) / 24) * 8;
    const int f0  = g * fpg;
    const int f1  = (f0 + fpg < nf) ? (f0 + fpg) : nf;
    if (f0 >= f1) return;

    const float4* xv = (const float4*)(x + (size_t)n * L_LEN * 384);
    float4*       ov = (float4*)(out + ((size_t)n * T + t_begin) * 384) + c;
    const float4  z  = make_float4(0.f, 0.f, 0.f, 0.f);

    int    cur = -2;
    float4 val = z;

    int f = f0;
    for (; f + 8 <= f1; f += 8) {
        // front-load 8 ids with two LDS.128 (f multiple of 8 -> aligned)
        const int4 ia = *(const int4*)&fidx[f];
        const int4 ib = *(const int4*)&fidx[f + 4];
        const int ids[8] = { ia.x, ia.y, ia.z, ia.w, ib.x, ib.y, ib.z, ib.w };

        float4* dst = ov + (size_t)f * 96;
        #pragma unroll
        for (int i = 0; i < 8; i++) {
            const int id = ids[i];
            if (id != cur) {               // warp-uniform
                val = (id >= 0) ? __ldg(&xv[(size_t)id * 96 + c]) : z;
                cur = id;
            }
            dst[(size_t)i * 96] = val;     // immediate STG.128
        }
    }
    // scalar tail (< 8 frames)
    for (; f < f1; f++) {
        const int id = fidx[f];
        if (id != cur) {
            val = (id >= 0) ? __ldg(&xv[(size_t)id * 96 + c]) : z;
            cur = id;
        }
        ov[(size_t)f * 96] = val;
    }
}

extern "C" void kernel_launch(void* const* d_in, const int* in_sizes, int n_in,
                              void* d_out, int out_size)
{
    const float* x   = (const float*)d_in[0];
    const int*   dur = (const int*)d_in[1];

    const int NL = in_sizes[1];            // N * L
    const int N  = NL / L_LEN;             // 64
    const int C  = in_sizes[0] / NL;       // 384 (layout assumes 384)

    const long long S    = (long long)out_size;
    const long long base = (long long)N * C;

    int T;
    int mel_is_i64 = 0;
    if (S % (base + 1) == 0) {
        T = (int)(S / (base + 1));         // case A: mel_pos as f32
    } else if (S % (base + 2) == 0) {
        T = (int)(S / (base + 2));         // case B: mel_pos as i64
        mel_is_i64 = 1;
    } else {
        T = (int)(S / base);               // fallback
    }

    float* out  = (float*)d_out;
    float* tail = out + (size_t)N * T * C;

    dim3 grid(N, SLICES);
    lr_onewave_kernel<<<grid, THREADS>>>(x, dur, out, tail, T, mel_is_i64);
}

// round 17
// speedup vs baseline: 1.1920x; 1.1920x over previous
#include <cuda_runtime.h>
#include <stdint.h>

// LengthRegulator, fused single-launch. LOCK-IN of the best-measured variant
// (R10: kernel 41.4us @ DRAM 60.5%, regs 26, occ 76.5%) for re-bench —
// bench-vs-kernel gap proved to be +-2-4us harness noise across rounds.
//
//   out[n, t, :] = x[n, searchsorted(csum[n], t, 'right'), :] for t < total[n], else 0
//   mel_pos = [1..T] appended after the frames.
//
// Output layout (validated via out_size divisibility, N*C = 24576):
//   case A: [ out: N*T*C f32 ][ mel_pos: T f32 ]
//   case B: [ out: N*T*C f32 ][ mel_pos: T i64 ]
//
// Proven-best structure: FRAMES=24 small self-balancing blocks (grid ~6336),
// 288 threads = 3 frame-groups x 96 channel chunks; warp-shuffle scan;
// 24 binary searches; copy loop = front-load 8 ids via two LDS.128, then per
// frame select source (register-cached float4, warp-uniform reload) and store
// IMMEDIATELY (8 independent STG.128). No staging arrays, no store hints,
// no software pipelining — each of those regressed when tested.

#define L_LEN    256
#define THREADS  288           // 3 frame-groups x 96 channel chunks
#define FRAMES   24
#define FPG      8

__global__ __launch_bounds__(THREADS)
void lr_fused_kernel(const float* __restrict__ x,
                     const int* __restrict__ dur,
                     float* __restrict__ out,
                     float* __restrict__ mp,
                     int T, int mel_is_i64)
{
    const int n    = blockIdx.y;
    const int t0   = blockIdx.x * FRAMES;
    const int tid  = threadIdx.x;
    const int wid  = tid >> 5;
    const int lane = tid & 31;

    __shared__ int csum[L_LEN];
    __shared__ int wsum[8];
    __shared__ int fidx[FRAMES];

    // ---- mel_pos: row-0 blocks write their 24 entries ----
    if (blockIdx.y == 0 && tid < FRAMES) {
        int t = t0 + tid;
        if (t < T) {
            if (mel_is_i64) ((long long*)mp)[t] = (long long)(t + 1);
            else            mp[t] = (float)(t + 1);
        }
    }

    // ---- inclusive prefix sum of durations (shuffle scan, warps 0..7) ----
    int v = 0;
    if (tid < L_LEN) {
        v = dur[n * L_LEN + tid];
        #pragma unroll
        for (int off = 1; off < 32; off <<= 1) {
            int u = __shfl_up_sync(0xFFFFFFFFu, v, off);
            if (lane >= off) v += u;
        }
        if (lane == 31) wsum[wid] = v;
    }
    __syncthreads();
    if (wid == 0 && lane < 8) {
        int s = wsum[lane];
        #pragma unroll
        for (int off = 1; off < 8; off <<= 1) {
            int u = __shfl_up_sync(0xFFu, s, off);
            if (lane >= off) s += u;
        }
        wsum[lane] = s;
    }
    __syncthreads();
    if (tid < L_LEN) csum[tid] = v + (wid > 0 ? wsum[wid - 1] : 0);
    __syncthreads();

    const int total = csum[L_LEN - 1];

    // ---- binary search source row for each of the 24 frames ----
    if (tid < FRAMES) {
        int t  = t0 + tid;
        int id = -1;
        if (t < T && t < total) {
            int lo = 0, hi = L_LEN;
            while (lo < hi) {
                int mid = (lo + hi) >> 1;
                if (csum[mid] > t) hi = mid; else lo = mid + 1;
            }
            id = (lo < L_LEN) ? lo : (L_LEN - 1);
        }
        fidx[tid] = id;
    }
    __syncthreads();

    // ---- streaming copy: proven-best loop shape ----
    const int g = tid / 96;                // frame-group 0..2 (whole warps)
    const int c = tid - g * 96;            // channel chunk 0..95

    const float4* xv = (const float4*)(x + (size_t)n * L_LEN * 384);
    float4*       ov = (float4*)(out + ((size_t)n * T + t0) * 384) + c;
    const float4  z  = make_float4(0.f, 0.f, 0.f, 0.f);

    int    cur = -2;
    float4 val = z;
    const int fb = g * FPG;

    if (t0 + FRAMES <= T) {
        // full block: front-load 8 ids (two LDS.128), unrolled select+store
        const int4 ia = ((const int4*)fidx)[g * 2];
        const int4 ib = ((const int4*)fidx)[g * 2 + 1];
        const int ids[FPG] = { ia.x, ia.y, ia.z, ia.w, ib.x, ib.y, ib.z, ib.w };

        float4* dst = ov + (size_t)fb * 96;
        #pragma unroll
        for (int i = 0; i < FPG; i++) {
            const int id = ids[i];
            if (id != cur) {               // warp-uniform
                val = (id >= 0) ? __ldg(&xv[(size_t)id * 96 + c]) : z;
                cur = id;
            }
            dst[(size_t)i * 96] = val;     // immediate STG.128
        }
    } else {
        // tail block (at most one per row)
        for (int i = 0; i < FPG; i++) {
            const int f = fb + i;
            if (t0 + f >= T) break;
            const int id = fidx[f];
            if (id != cur) {
                val = (id >= 0) ? __ldg(&xv[(size_t)id * 96 + c]) : z;
                cur = id;
            }
            ov[(size_t)f * 96] = val;
        }
    }
}

extern "C" void kernel_launch(void* const* d_in, const int* in_sizes, int n_in,
                              void* d_out, int out_size)
{
    const float* x   = (const float*)d_in[0];
    const int*   dur = (const int*)d_in[1];

    const int NL = in_sizes[1];            // N * L
    const int N  = NL / L_LEN;             // 64
    const int C  = in_sizes[0] / NL;       // 384 (layout assumes 384)

    const long long S    = (long long)out_size;
    const long long base = (long long)N * C;

    int T;
    int mel_is_i64 = 0;
    if (S % (base + 1) == 0) {
        T = (int)(S / (base + 1));         // case A: mel_pos as f32
    } else if (S % (base + 2) == 0) {
        T = (int)(S / (base + 2));         // case B: mel_pos as i64
        mel_is_i64 = 1;
    } else {
        T = (int)(S / base);               // fallback
    }

    float* out  = (float*)d_out;
    float* tail = out + (size_t)N * T * C;

    dim3 grid((T + FRAMES - 1) / FRAMES, N);
    lr_fused_kernel<<<grid, THREADS>>>(x, dur, out, tail, T, mel_is_i64);
}